// round 10
// baseline (speedup 1.0000x reference)
#include <cuda_runtime.h>
#include <cuda_bf16.h>

// ---------------------------------------------------------------------------
// Problem constants (fixed by the reference)
// ---------------------------------------------------------------------------
#define CLOUDS   4
#define NPTS     16384
#define MCENT    4096            // RATIO * NPTS
#define MAXNB    64
#define R2       0.0625f         // 0.25^2
#define CLUSTER  4               // CTAs per cloud
#define PTS_PER_CTA (NPTS / CLUSTER)   // 4096
#define FPS_THREADS 1024
#define PPT      4               // points per thread

#define OUT_XC   0                      // x_centers  [16384*3]
#define OUT_POS  (CLOUDS*MCENT*3)       // pos[idx]   [16384*3]
#define OUT_BAT  (CLOUDS*MCENT*6)       // batch[idx] [16384]

// Device scratch (no cudaMalloc allowed)
__device__ float g_pos6[(size_t)CLOUDS * NPTS * 8];  // padded to 8 floats/pt
__device__ int   g_idx[CLOUDS * MCENT];

// ---------------------------------------------------------------------------
// f32x2 helpers (bit-exact packed math)
// ---------------------------------------------------------------------------
__device__ __forceinline__ unsigned long long pack2(float lo, float hi) {
    unsigned long long r;
    asm("mov.b64 %0, {%1, %2};" : "=l"(r) : "f"(lo), "f"(hi));
    return r;
}
__device__ __forceinline__ void unpack2(unsigned long long v,
                                        float& lo, float& hi) {
    asm("mov.b64 {%0, %1}, %2;" : "=f"(lo), "=f"(hi) : "l"(v));
}
__device__ __forceinline__ unsigned long long fma2(unsigned long long a,
                                                   unsigned long long b,
                                                   unsigned long long c) {
    unsigned long long r;
    asm("fma.rn.f32x2 %0, %1, %2, %3;"
        : "=l"(r) : "l"(a), "l"(b), "l"(c));
    return r;
}

// ---------------------------------------------------------------------------
// 6-D squared distance (scalar form for the neighbor kernel).
// FMA left fold matches XLA:GPU contraction of sum((p-c)**2, axis=-1).
// ---------------------------------------------------------------------------
__device__ __forceinline__ float dist6(float p0, float p1, float p2,
                                       float p3, float p4, float p5,
                                       float c0, float c1, float c2,
                                       float c3, float c4, float c5) {
    float t, d;
    t = __fsub_rn(p0, c0); d = __fmul_rn(t, t);
    t = __fsub_rn(p1, c1); d = __fmaf_rn(t, t, d);
    t = __fsub_rn(p2, c2); d = __fmaf_rn(t, t, d);
    t = __fsub_rn(p3, c3); d = __fmaf_rn(t, t, d);
    t = __fsub_rn(p4, c4); d = __fmaf_rn(t, t, d);
    t = __fsub_rn(p5, c5); d = __fmaf_rn(t, t, d);
    return d;
}

__device__ __forceinline__ unsigned redux_max_u32(unsigned v, unsigned mask) {
    unsigned r;
    asm("redux.sync.max.u32 %0, %1, %2;" : "=r"(r) : "r"(v), "r"(mask));
    return r;
}

// ---------------------------------------------------------------------------
// Kernel A: build padded pos6 = [x0 x1 x2 p0 p1 p2 0 0] per point
// ---------------------------------------------------------------------------
__global__ void prep_kernel(const float* __restrict__ x,
                            const float* __restrict__ pos) {
    int i = blockIdx.x * blockDim.x + threadIdx.x;
    if (i >= CLOUDS * NPTS) return;
    float4 r0 = make_float4(x[3 * i], x[3 * i + 1], x[3 * i + 2], pos[3 * i]);
    float4 r1 = make_float4(pos[3 * i + 1], pos[3 * i + 2], 0.f, 0.f);
    float4* dst = reinterpret_cast<float4*>(g_pos6);
    dst[2 * i] = r0;
    dst[2 * i + 1] = r1;
}

// ---------------------------------------------------------------------------
// Kernel B: FPS v7. 4-CTA cluster per cloud, 1024 thr/CTA, 4 pts/thread.
// Narrow exchange: 4 senders x 2 st.async.v2.b64 -> 8 events per barrier.
// Slots carry only (key, idx); winner coords looked up in the CTA's smem
// point cache (128 KB dynamic smem).
// Candidate record = 8 u32: {keybits, cloud_idx, c0,c1,c2,c3,c4,c5}.
// ---------------------------------------------------------------------------
struct FpsShm {
    uint4 candbuf[2][CLUSTER][2];   // [parity][sender rank][32B]
    unsigned long long mbar[2];
    unsigned slotkey[32];           // per-warp winner keybits
    unsigned slotidx[32];           // per-warp winner cloud-local idx
    float4 pts[PTS_PER_CTA * 2];    // this CTA's points (float4 pairs)
};

__global__ void __launch_bounds__(FPS_THREADS, 1)
fps_kernel() {
    extern __shared__ unsigned char smraw[];
    FpsShm* sh = reinterpret_cast<FpsShm*>(smraw);

    unsigned rank;
    asm("mov.u32 %0, %%cluster_ctarank;" : "=r"(rank));
    const int cloud = blockIdx.x / CLUSTER;
    const int tid = threadIdx.x;
    const int wid = tid >> 5;
    const int lane = tid & 31;

    const float4* gp = reinterpret_cast<const float4*>(
        g_pos6 + (size_t)cloud * NPTS * 8);

    const int lbase = tid * PPT;                       // CTA-local point base
    const int gbase = (int)rank * PTS_PER_CTA + lbase; // cloud-local

    unsigned long long P[PPT][3];
    float mind[PPT];
    const unsigned long long NEG1 = pack2(-1.0f, -1.0f);
#pragma unroll
    for (int j = 0; j < PPT; ++j) {
        float4 q0 = gp[2 * (gbase + j)], q1 = gp[2 * (gbase + j) + 1];
        P[j][0] = pack2(q0.x, q0.y);
        P[j][1] = pack2(q0.z, q0.w);
        P[j][2] = pack2(q1.x, q1.y);
        sh->pts[2 * (lbase + j)] = q0;
        sh->pts[2 * (lbase + j) + 1] = q1;
        mind[j] = __int_as_float(0x7f800000);
    }

    // current winner coords; pick 0 = point 0 of the cloud
    float4 p0 = gp[0], p1 = gp[1];
    float w0 = p0.x, w1 = p0.y, w2 = p0.z, w3 = p0.w, w4 = p1.x, w5 = p1.y;

    if (tid == 0) {
        unsigned m0 = (unsigned)__cvta_generic_to_shared(&sh->mbar[0]);
        unsigned m1 = (unsigned)__cvta_generic_to_shared(&sh->mbar[1]);
        asm volatile("mbarrier.init.shared.b64 [%0], 1;" :: "r"(m0) : "memory");
        asm volatile("mbarrier.init.shared.b64 [%0], 1;" :: "r"(m1) : "memory");
        asm volatile("fence.mbarrier_init.release.cluster;" ::: "memory");
        if (rank == 0) g_idx[cloud * MCENT] = cloud * NPTS;
    }
    __syncthreads();
    // make mbarrier init visible cluster-wide before any peer st.async
    asm volatile("barrier.cluster.arrive.aligned;" ::: "memory");
    asm volatile("barrier.cluster.wait.aligned;"   ::: "memory");

    // loop-invariant peer addresses for the senders (warp0, lanes 0..3)
    unsigned dr0 = 0, dr1 = 0, mr0 = 0, mr1 = 0;
    if (wid == 0 && lane < CLUSTER) {
        unsigned dl0 = (unsigned)__cvta_generic_to_shared(&sh->candbuf[0][rank][0]);
        unsigned dl1 = (unsigned)__cvta_generic_to_shared(&sh->candbuf[1][rank][0]);
        unsigned ml0 = (unsigned)__cvta_generic_to_shared(&sh->mbar[0]);
        unsigned ml1 = (unsigned)__cvta_generic_to_shared(&sh->mbar[1]);
        asm("mapa.shared::cluster.u32 %0, %1, %2;" : "=r"(dr0) : "r"(dl0), "r"(lane));
        asm("mapa.shared::cluster.u32 %0, %1, %2;" : "=r"(dr1) : "r"(dl1), "r"(lane));
        asm("mapa.shared::cluster.u32 %0, %1, %2;" : "=r"(mr0) : "r"(ml0), "r"(lane));
        asm("mapa.shared::cluster.u32 %0, %1, %2;" : "=r"(mr1) : "r"(ml1), "r"(lane));
    }
    const unsigned mb0 = (unsigned)__cvta_generic_to_shared(&sh->mbar[0]);
    const unsigned mb1 = (unsigned)__cvta_generic_to_shared(&sh->mbar[1]);

    unsigned ph0 = 0, ph1 = 0;

#pragma unroll 1
    for (int k = 1; k < MCENT; ++k) {
        const int par = k & 1;
        if (tid == 0) {   // expected tx: 4 senders x 32 bytes
            asm volatile("mbarrier.arrive.expect_tx.shared.b64 _, [%0], %1;"
                         :: "r"(par ? mb1 : mb0), "r"(128u) : "memory");
        }
        // ---- distances to current winner; thread-best (idx ascending) ----
        unsigned long long W01 = pack2(w0, w1);
        unsigned long long W23 = pack2(w2, w3);
        unsigned long long W45 = pack2(w4, w5);
        unsigned bk = 0;
        unsigned bidx = (unsigned)gbase;
#pragma unroll
        for (int j = 0; j < PPT; ++j) {
            unsigned long long T01 = fma2(W01, NEG1, P[j][0]);
            unsigned long long T23 = fma2(W23, NEG1, P[j][1]);
            unsigned long long T45 = fma2(W45, NEG1, P[j][2]);
            float t0, t1, t2, t3, t4, t5;
            unpack2(T01, t0, t1);
            unpack2(T23, t2, t3);
            unpack2(T45, t4, t5);
            float d = __fmul_rn(t0, t0);
            d = __fmaf_rn(t1, t1, d);
            d = __fmaf_rn(t2, t2, d);
            d = __fmaf_rn(t3, t3, d);
            d = __fmaf_rn(t4, t4, d);
            d = __fmaf_rn(t5, t5, d);
            mind[j] = fminf(mind[j], d);
            unsigned kbj = __float_as_uint(mind[j]);
            if (kbj > bk) { bk = kbj; bidx = (unsigned)(gbase + j); }
        }

        // ---- warp argmax: redux + ballot (lowest lane = lowest idx) ----
        unsigned m = redux_max_u32(bk, 0xffffffffu);
        unsigned bal = __ballot_sync(0xffffffffu, bk == m);
        if (lane == __ffs(bal) - 1) {
            sh->slotkey[wid] = m;
            sh->slotidx[wid] = bidx;
        }
        __syncthreads();   // bar(1): slots ready

        if (wid == 0) {
            // ---- CTA argmax over 32 warp slots (slot order = idx order) ----
            unsigned kw = sh->slotkey[lane];
            unsigned M = redux_max_u32(kw, 0xffffffffu);
            unsigned bb = __ballot_sync(0xffffffffu, kw == M);
            int s = __ffs(bb) - 1;
            unsigned widx = sh->slotidx[s];
            unsigned loc = widx & (PTS_PER_CTA - 1);
            float4 c0 = sh->pts[2 * loc];       // broadcast LDS
            float4 c1 = sh->pts[2 * loc + 1];
            if (lane < CLUSTER) {
                unsigned long long q0 =
                    (unsigned long long)M | ((unsigned long long)widx << 32);
                unsigned long long q1 = pack2(c0.x, c0.y);
                unsigned long long q2 = pack2(c0.z, c0.w);
                unsigned long long q3 = pack2(c1.x, c1.y);
                unsigned dr = par ? dr1 : dr0;
                unsigned mr = par ? mr1 : mr0;
                asm volatile(
                    "st.async.shared::cluster.mbarrier::complete_tx::bytes.v2.b64 [%0], {%1, %2}, [%3];"
                    :: "r"(dr), "l"(q0), "l"(q1), "r"(mr) : "memory");
                asm volatile(
                    "st.async.shared::cluster.mbarrier::complete_tx::bytes.v2.b64 [%0], {%1, %2}, [%3];"
                    :: "r"(dr + 16), "l"(q2), "l"(q3), "r"(mr) : "memory");
            }
            // ---- warp0 alone waits for the 4 candidates ----
            unsigned mb = par ? mb1 : mb0;
            unsigned ph = par ? ph1 : ph0;
            unsigned done;
            do {
                asm volatile(
                    "{ .reg .pred p;\n\t"
                    "mbarrier.try_wait.parity.acquire.cta.shared::cta.b64 p, [%1], %2, 0x989680;\n\t"
                    "selp.b32 %0, 1, 0, p; }"
                    : "=r"(done) : "r"(mb), "r"(ph) : "memory");
            } while (!done);
        }
        if (par) ph1 ^= 1; else ph0 ^= 1;
        __syncthreads();   // bar(2): candbuf complete for everyone

        // ---- ALL warps resolve cluster winner into registers (parallel) ----
        {
            unsigned kc = sh->candbuf[par][lane & (CLUSTER - 1)][0].x;
            unsigned M2 = redux_max_u32(kc, 0xffffffffu);
            unsigned b2 = __ballot_sync(0xffffffffu, kc == M2);
            int s2 = __ffs(b2) - 1;          // lowest lane -> lowest rank
            uint4 r0 = sh->candbuf[par][s2][0];
            uint4 r1 = sh->candbuf[par][s2][1];
            w0 = __uint_as_float(r0.z); w1 = __uint_as_float(r0.w);
            w2 = __uint_as_float(r1.x); w3 = __uint_as_float(r1.y);
            w4 = __uint_as_float(r1.z); w5 = __uint_as_float(r1.w);
            if (rank == 0 && tid == 0)
                g_idx[cloud * MCENT + k] = cloud * NPTS + (int)r0.y;
        }
    }
}

// ---------------------------------------------------------------------------
// Kernel C: radius neighbors + mean.  One warp per center; ordered first-64
// take via ballot so capping matches top_k-on-index semantics exactly.
// ---------------------------------------------------------------------------
__global__ void __launch_bounds__(256)
nbr_kernel(float* __restrict__ out, int out_size) {
    int w = (blockIdx.x * blockDim.x + threadIdx.x) >> 5;
    int lane = threadIdx.x & 31;
    if (w >= CLOUDS * MCENT) return;
    int cloud = w >> 12;                 // 4096 centers per cloud
    int g = g_idx[w];
    int lc = g - cloud * NPTS;

    const float4* gp = reinterpret_cast<const float4*>(
        g_pos6 + (size_t)cloud * NPTS * 8);
    float4 c0 = gp[2 * lc], c1 = gp[2 * lc + 1];

    float sx = 0.f, sy = 0.f, sz = 0.f;
    int cnt = 0;
    for (int base = 0; base < NPTS; base += 32) {
        int i = base + lane;
        float4 a0 = gp[2 * i], a1 = gp[2 * i + 1];
        float d = dist6(a0.x, a0.y, a0.z, a0.w, a1.x, a1.y,
                        c0.x, c0.y, c0.z, c0.w, c1.x, c1.y);
        bool pred = (d <= R2);
        unsigned mask = __ballot_sync(0xffffffffu, pred);
        int need = MAXNB - cnt;
        int rk = __popc(mask & ((1u << lane) - 1u));
        if (pred && rk < need) { sx += a0.x; sy += a0.y; sz += a0.z; }
        int c = __popc(mask);
        cnt += (c < need) ? c : need;
        if (cnt >= MAXNB) break;         // warp-uniform
    }
#pragma unroll
    for (int s = 16; s > 0; s >>= 1) {
        sx += __shfl_down_sync(0xffffffffu, sx, s);
        sy += __shfl_down_sync(0xffffffffu, sy, s);
        sz += __shfl_down_sync(0xffffffffu, sz, s);
    }
    if (lane == 0) {
        float c = (float)cnt;            // self always in radius -> cnt >= 1
        if (OUT_XC + w * 3 + 2 < out_size) {
            out[OUT_XC + w * 3 + 0] = sx / c;
            out[OUT_XC + w * 3 + 1] = sy / c;
            out[OUT_XC + w * 3 + 2] = sz / c;
        }
    }
}

// ---------------------------------------------------------------------------
// Kernel D: gather pos[idx] and batch[idx]
// ---------------------------------------------------------------------------
__global__ void sample_kernel(const float* __restrict__ pos,
                              float* __restrict__ out, int out_size) {
    int c = blockIdx.x * blockDim.x + threadIdx.x;
    if (c >= CLOUDS * MCENT) return;
    int g = g_idx[c];
    if (OUT_POS + c * 3 + 2 < out_size) {
        out[OUT_POS + c * 3 + 0] = pos[3 * g + 0];
        out[OUT_POS + c * 3 + 1] = pos[3 * g + 1];
        out[OUT_POS + c * 3 + 2] = pos[3 * g + 2];
    }
    if (OUT_BAT + c < out_size)
        out[OUT_BAT + c] = (float)(g >> 14);   // batch id = g / NPTS
}

// ---------------------------------------------------------------------------
extern "C" void kernel_launch(void* const* d_in, const int* in_sizes, int n_in,
                              void* d_out, int out_size) {
    const float* x   = (const float*)d_in[0];
    const float* pos = (const float*)d_in[1];
    float* out = (float*)d_out;

    prep_kernel<<<(CLOUDS * NPTS + 255) / 256, 256>>>(x, pos);

    cudaFuncSetAttribute(fps_kernel,
                         cudaFuncAttributeMaxDynamicSharedMemorySize,
                         (int)sizeof(FpsShm));
    cudaLaunchConfig_t cfg = {};
    cfg.gridDim = dim3(CLOUDS * CLUSTER, 1, 1);
    cfg.blockDim = dim3(FPS_THREADS, 1, 1);
    cfg.dynamicSmemBytes = sizeof(FpsShm);
    cfg.stream = 0;
    cudaLaunchAttribute attrs[1];
    attrs[0].id = cudaLaunchAttributeClusterDimension;
    attrs[0].val.clusterDim.x = CLUSTER;
    attrs[0].val.clusterDim.y = 1;
    attrs[0].val.clusterDim.z = 1;
    cfg.attrs = attrs;
    cfg.numAttrs = 1;
    cudaLaunchKernelEx(&cfg, fps_kernel);

    nbr_kernel<<<(CLOUDS * MCENT * 32) / 256, 256>>>(out, out_size);
    sample_kernel<<<(CLOUDS * MCENT + 255) / 256, 256>>>(pos, out, out_size);
}

// round 11
// speedup vs baseline: 1.3093x; 1.3093x over previous
#include <cuda_runtime.h>
#include <cuda_bf16.h>

// ---------------------------------------------------------------------------
// Problem constants (fixed by the reference)
// ---------------------------------------------------------------------------
#define CLOUDS   4
#define NPTS     16384
#define MCENT    4096            // RATIO * NPTS
#define MAXNB    64
#define R2       0.0625f         // 0.25^2
#define CLUSTER  16              // nonportable cluster size
#define PTS_PER_CTA (NPTS / CLUSTER)   // 1024
#define FPS_THREADS 256
#define PPT      4               // points per thread
#define NWARPS   (FPS_THREADS / 32)    // 8

#define OUT_XC   0                      // x_centers  [16384*3]
#define OUT_POS  (CLOUDS*MCENT*3)       // pos[idx]   [16384*3]
#define OUT_BAT  (CLOUDS*MCENT*6)       // batch[idx] [16384]

// Device scratch (no cudaMalloc allowed)
__device__ float g_pos6[(size_t)CLOUDS * NPTS * 8];  // padded to 8 floats/pt
__device__ int   g_idx[CLOUDS * MCENT];

// ---------------------------------------------------------------------------
// f32x2 helpers (bit-exact packed math)
// ---------------------------------------------------------------------------
__device__ __forceinline__ unsigned long long pack2(float lo, float hi) {
    unsigned long long r;
    asm("mov.b64 %0, {%1, %2};" : "=l"(r) : "f"(lo), "f"(hi));
    return r;
}
__device__ __forceinline__ void unpack2(unsigned long long v,
                                        float& lo, float& hi) {
    asm("mov.b64 {%0, %1}, %2;" : "=f"(lo), "=f"(hi) : "l"(v));
}
__device__ __forceinline__ unsigned long long fma2(unsigned long long a,
                                                   unsigned long long b,
                                                   unsigned long long c) {
    unsigned long long r;
    asm("fma.rn.f32x2 %0, %1, %2, %3;"
        : "=l"(r) : "l"(a), "l"(b), "l"(c));
    return r;
}

// ---------------------------------------------------------------------------
// 6-D squared distance (scalar form for the neighbor kernel).
// FMA left fold matches XLA:GPU contraction of sum((p-c)**2, axis=-1).
// ---------------------------------------------------------------------------
__device__ __forceinline__ float dist6(float p0, float p1, float p2,
                                       float p3, float p4, float p5,
                                       float c0, float c1, float c2,
                                       float c3, float c4, float c5) {
    float t, d;
    t = __fsub_rn(p0, c0); d = __fmul_rn(t, t);
    t = __fsub_rn(p1, c1); d = __fmaf_rn(t, t, d);
    t = __fsub_rn(p2, c2); d = __fmaf_rn(t, t, d);
    t = __fsub_rn(p3, c3); d = __fmaf_rn(t, t, d);
    t = __fsub_rn(p4, c4); d = __fmaf_rn(t, t, d);
    t = __fsub_rn(p5, c5); d = __fmaf_rn(t, t, d);
    return d;
}

__device__ __forceinline__ unsigned redux_max_u32(unsigned v, unsigned mask) {
    unsigned r;
    asm("redux.sync.max.u32 %0, %1, %2;" : "=r"(r) : "r"(v), "r"(mask));
    return r;
}

// ---------------------------------------------------------------------------
// Kernel A: build padded pos6 = [x0 x1 x2 p0 p1 p2 0 0] per point
// ---------------------------------------------------------------------------
__global__ void prep_kernel(const float* __restrict__ x,
                            const float* __restrict__ pos) {
    int i = blockIdx.x * blockDim.x + threadIdx.x;
    if (i >= CLOUDS * NPTS) return;
    float4 r0 = make_float4(x[3 * i], x[3 * i + 1], x[3 * i + 2], pos[3 * i]);
    float4 r1 = make_float4(pos[3 * i + 1], pos[3 * i + 2], 0.f, 0.f);
    float4* dst = reinterpret_cast<float4*>(g_pos6);
    dst[2 * i] = r0;
    dst[2 * i + 1] = r1;
}

// ---------------------------------------------------------------------------
// Kernel B: FPS v8. 16-CTA cluster per cloud, 256 thr/CTA, 4 pts/thread.
// Same points/CTA as the champion (same compute drain) but 8-warp bars and
// an 8-slot CTA reduce. All 32 lanes of warp0 send: lane i ships one 16B
// v2.b64 half-record to CTA i>>1.
// Candidate record = 8 u32: {keybits, cloud_idx, c0,c1,c2,c3,c4,c5}.
// ---------------------------------------------------------------------------
__global__ void __launch_bounds__(FPS_THREADS, 1)
fps_kernel() {
    __shared__ unsigned long long mbar[2];
    __shared__ uint4 candbuf[2][CLUSTER][2];   // [parity][sender rank][32B]
    __shared__ unsigned slotkey[NWARPS];       // per-warp winner keybits
    __shared__ uint4 slotc[NWARPS][2];         // per-warp winner record

    unsigned rank;
    asm("mov.u32 %0, %%cluster_ctarank;" : "=r"(rank));
    const int cloud = blockIdx.x / CLUSTER;
    const int tid = threadIdx.x;
    const int wid = tid >> 5;
    const int lane = tid & 31;

    const float4* gp = reinterpret_cast<const float4*>(
        g_pos6 + (size_t)cloud * NPTS * 8);

    const int gbase = (int)rank * PTS_PER_CTA + tid * PPT;  // cloud-local

    unsigned long long P[PPT][3];
    float mind[PPT];
    const unsigned long long NEG1 = pack2(-1.0f, -1.0f);
#pragma unroll
    for (int j = 0; j < PPT; ++j) {
        float4 q0 = gp[2 * (gbase + j)], q1 = gp[2 * (gbase + j) + 1];
        P[j][0] = pack2(q0.x, q0.y);
        P[j][1] = pack2(q0.z, q0.w);
        P[j][2] = pack2(q1.x, q1.y);
        mind[j] = __int_as_float(0x7f800000);
    }

    // current winner coords; pick 0 = point 0 of the cloud
    float4 p0 = gp[0], p1 = gp[1];
    float w0 = p0.x, w1 = p0.y, w2 = p0.z, w3 = p0.w, w4 = p1.x, w5 = p1.y;

    if (tid == 0) {
        unsigned m0 = (unsigned)__cvta_generic_to_shared(&mbar[0]);
        unsigned m1 = (unsigned)__cvta_generic_to_shared(&mbar[1]);
        asm volatile("mbarrier.init.shared.b64 [%0], 1;" :: "r"(m0) : "memory");
        asm volatile("mbarrier.init.shared.b64 [%0], 1;" :: "r"(m1) : "memory");
        asm volatile("fence.mbarrier_init.release.cluster;" ::: "memory");
        if (rank == 0) g_idx[cloud * MCENT] = cloud * NPTS;
    }
    __syncthreads();
    // make mbarrier init visible cluster-wide before any peer st.async
    asm volatile("barrier.cluster.arrive.aligned;" ::: "memory");
    asm volatile("barrier.cluster.wait.aligned;"   ::: "memory");

    // loop-invariant peer addresses: lane i -> CTA i>>1, half (i&1)*16B
    unsigned dr0 = 0, dr1 = 0, mr0 = 0, mr1 = 0;
    if (wid == 0) {
        unsigned dst = (unsigned)(lane >> 1);
        unsigned half = (unsigned)(lane & 1) * 16u;
        unsigned dl0 = (unsigned)__cvta_generic_to_shared(&candbuf[0][rank][0]) + half;
        unsigned dl1 = (unsigned)__cvta_generic_to_shared(&candbuf[1][rank][0]) + half;
        unsigned ml0 = (unsigned)__cvta_generic_to_shared(&mbar[0]);
        unsigned ml1 = (unsigned)__cvta_generic_to_shared(&mbar[1]);
        asm("mapa.shared::cluster.u32 %0, %1, %2;" : "=r"(dr0) : "r"(dl0), "r"(dst));
        asm("mapa.shared::cluster.u32 %0, %1, %2;" : "=r"(dr1) : "r"(dl1), "r"(dst));
        asm("mapa.shared::cluster.u32 %0, %1, %2;" : "=r"(mr0) : "r"(ml0), "r"(dst));
        asm("mapa.shared::cluster.u32 %0, %1, %2;" : "=r"(mr1) : "r"(ml1), "r"(dst));
    }
    const unsigned mb0 = (unsigned)__cvta_generic_to_shared(&mbar[0]);
    const unsigned mb1 = (unsigned)__cvta_generic_to_shared(&mbar[1]);

    unsigned ph0 = 0, ph1 = 0;

#pragma unroll 1
    for (int k = 1; k < MCENT; ++k) {
        const int par = k & 1;
        if (tid == 0) {   // expected tx: 16 CTAs x 32 bytes
            asm volatile("mbarrier.arrive.expect_tx.shared.b64 _, [%0], %1;"
                         :: "r"(par ? mb1 : mb0), "r"(512u) : "memory");
        }
        // ---- distances to current winner; thread-best (idx ascending) ----
        unsigned long long W01 = pack2(w0, w1);
        unsigned long long W23 = pack2(w2, w3);
        unsigned long long W45 = pack2(w4, w5);
        unsigned bk = 0;
        unsigned bj = 0;
#pragma unroll
        for (int j = 0; j < PPT; ++j) {
            unsigned long long T01 = fma2(W01, NEG1, P[j][0]);
            unsigned long long T23 = fma2(W23, NEG1, P[j][1]);
            unsigned long long T45 = fma2(W45, NEG1, P[j][2]);
            float t0, t1, t2, t3, t4, t5;
            unpack2(T01, t0, t1);
            unpack2(T23, t2, t3);
            unpack2(T45, t4, t5);
            float d = __fmul_rn(t0, t0);
            d = __fmaf_rn(t1, t1, d);
            d = __fmaf_rn(t2, t2, d);
            d = __fmaf_rn(t3, t3, d);
            d = __fmaf_rn(t4, t4, d);
            d = __fmaf_rn(t5, t5, d);
            mind[j] = fminf(mind[j], d);
            unsigned kbj = __float_as_uint(mind[j]);
            if (kbj > bk) { bk = kbj; bj = (unsigned)j; }   // strict: ties->low j
        }

        // ---- warp argmax: redux + ballot (lowest lane = lowest idx) ----
        unsigned m = redux_max_u32(bk, 0xffffffffu);
        unsigned bal = __ballot_sync(0xffffffffu, bk == m);
        if (lane == __ffs(bal) - 1) {
            // select winning point's packed coords from registers
            unsigned long long C0 = P[0][0], C1 = P[0][1], C2 = P[0][2];
#pragma unroll
            for (int j = 1; j < PPT; ++j)
                if ((unsigned)j == bj) { C0 = P[j][0]; C1 = P[j][1]; C2 = P[j][2]; }
            float c0x, c0y, c0z, c0w, c1x, c1y;
            unpack2(C0, c0x, c0y);
            unpack2(C1, c0z, c0w);
            unpack2(C2, c1x, c1y);
            slotkey[wid] = m;
            slotc[wid][0] = make_uint4(m, (unsigned)(gbase + (int)bj),
                                       __float_as_uint(c0x),
                                       __float_as_uint(c0y));
            slotc[wid][1] = make_uint4(__float_as_uint(c0z),
                                       __float_as_uint(c0w),
                                       __float_as_uint(c1x),
                                       __float_as_uint(c1y));
        }
        __syncthreads();   // bar(1): 8 slots ready

        if (wid == 0) {
            // ---- CTA argmax over 8 warp slots (slot order = idx order) ----
            unsigned kw = slotkey[lane & (NWARPS - 1)];
            unsigned M = redux_max_u32(kw, 0xffffffffu);
            unsigned bb = __ballot_sync(0xffffffffu, kw == M);
            int s = __ffs(bb) - 1;          // lowest lane = lowest warp
            // all 32 lanes send one 16B half-record: lane i -> CTA i>>1
            {
                const unsigned long long* src =
                    reinterpret_cast<const unsigned long long*>(&slotc[s][0]);
                unsigned h = (unsigned)(lane & 1) * 2u;
                unsigned long long qa = src[h], qb = src[h + 1];
                unsigned dr = par ? dr1 : dr0;
                unsigned mr = par ? mr1 : mr0;
                asm volatile(
                    "st.async.shared::cluster.mbarrier::complete_tx::bytes.v2.b64 [%0], {%1, %2}, [%3];"
                    :: "r"(dr), "l"(qa), "l"(qb), "r"(mr) : "memory");
            }
            // ---- warp0 alone waits for the 16 candidates ----
            unsigned mb = par ? mb1 : mb0;
            unsigned ph = par ? ph1 : ph0;
            unsigned done;
            do {
                asm volatile(
                    "{ .reg .pred p;\n\t"
                    "mbarrier.try_wait.parity.acquire.cta.shared::cta.b64 p, [%1], %2, 0x989680;\n\t"
                    "selp.b32 %0, 1, 0, p; }"
                    : "=r"(done) : "r"(mb), "r"(ph) : "memory");
            } while (!done);
        }
        if (par) ph1 ^= 1; else ph0 ^= 1;
        __syncthreads();   // bar(2): candbuf complete for everyone

        // ---- ALL warps resolve cluster winner into registers (parallel) ----
        {
            unsigned kc = candbuf[par][lane & (CLUSTER - 1)][0].x;
            unsigned M2 = redux_max_u32(kc, 0xffffffffu);
            unsigned b2 = __ballot_sync(0xffffffffu, kc == M2);
            int s2 = __ffs(b2) - 1;          // lowest lane -> lowest rank
            uint4 r0 = candbuf[par][s2][0];
            uint4 r1 = candbuf[par][s2][1];
            w0 = __uint_as_float(r0.z); w1 = __uint_as_float(r0.w);
            w2 = __uint_as_float(r1.x); w3 = __uint_as_float(r1.y);
            w4 = __uint_as_float(r1.z); w5 = __uint_as_float(r1.w);
            if (rank == 0 && tid == 0)
                g_idx[cloud * MCENT + k] = cloud * NPTS + (int)r0.y;
        }
    }
}

// ---------------------------------------------------------------------------
// Kernel C: radius neighbors + mean.  One warp per center; ordered first-64
// take via ballot so capping matches top_k-on-index semantics exactly.
// ---------------------------------------------------------------------------
__global__ void __launch_bounds__(256)
nbr_kernel(float* __restrict__ out, int out_size) {
    int w = (blockIdx.x * blockDim.x + threadIdx.x) >> 5;
    int lane = threadIdx.x & 31;
    if (w >= CLOUDS * MCENT) return;
    int cloud = w >> 12;                 // 4096 centers per cloud
    int g = g_idx[w];
    int lc = g - cloud * NPTS;

    const float4* gp = reinterpret_cast<const float4*>(
        g_pos6 + (size_t)cloud * NPTS * 8);
    float4 c0 = gp[2 * lc], c1 = gp[2 * lc + 1];

    float sx = 0.f, sy = 0.f, sz = 0.f;
    int cnt = 0;
    for (int base = 0; base < NPTS; base += 32) {
        int i = base + lane;
        float4 a0 = gp[2 * i], a1 = gp[2 * i + 1];
        float d = dist6(a0.x, a0.y, a0.z, a0.w, a1.x, a1.y,
                        c0.x, c0.y, c0.z, c0.w, c1.x, c1.y);
        bool pred = (d <= R2);
        unsigned mask = __ballot_sync(0xffffffffu, pred);
        int need = MAXNB - cnt;
        int rk = __popc(mask & ((1u << lane) - 1u));
        if (pred && rk < need) { sx += a0.x; sy += a0.y; sz += a0.z; }
        int c = __popc(mask);
        cnt += (c < need) ? c : need;
        if (cnt >= MAXNB) break;         // warp-uniform
    }
#pragma unroll
    for (int s = 16; s > 0; s >>= 1) {
        sx += __shfl_down_sync(0xffffffffu, sx, s);
        sy += __shfl_down_sync(0xffffffffu, sy, s);
        sz += __shfl_down_sync(0xffffffffu, sz, s);
    }
    if (lane == 0) {
        float c = (float)cnt;            // self always in radius -> cnt >= 1
        if (OUT_XC + w * 3 + 2 < out_size) {
            out[OUT_XC + w * 3 + 0] = sx / c;
            out[OUT_XC + w * 3 + 1] = sy / c;
            out[OUT_XC + w * 3 + 2] = sz / c;
        }
    }
}

// ---------------------------------------------------------------------------
// Kernel D: gather pos[idx] and batch[idx]
// ---------------------------------------------------------------------------
__global__ void sample_kernel(const float* __restrict__ pos,
                              float* __restrict__ out, int out_size) {
    int c = blockIdx.x * blockDim.x + threadIdx.x;
    if (c >= CLOUDS * MCENT) return;
    int g = g_idx[c];
    if (OUT_POS + c * 3 + 2 < out_size) {
        out[OUT_POS + c * 3 + 0] = pos[3 * g + 0];
        out[OUT_POS + c * 3 + 1] = pos[3 * g + 1];
        out[OUT_POS + c * 3 + 2] = pos[3 * g + 2];
    }
    if (OUT_BAT + c < out_size)
        out[OUT_BAT + c] = (float)(g >> 14);   // batch id = g / NPTS
}

// ---------------------------------------------------------------------------
extern "C" void kernel_launch(void* const* d_in, const int* in_sizes, int n_in,
                              void* d_out, int out_size) {
    const float* x   = (const float*)d_in[0];
    const float* pos = (const float*)d_in[1];
    float* out = (float*)d_out;

    prep_kernel<<<(CLOUDS * NPTS + 255) / 256, 256>>>(x, pos);

    // FPS: 16-CTA clusters (nonportable size) via cudaLaunchKernelEx
    cudaFuncSetAttribute(fps_kernel,
                         cudaFuncAttributeNonPortableClusterSizeAllowed, 1);
    cudaLaunchConfig_t cfg = {};
    cfg.gridDim = dim3(CLOUDS * CLUSTER, 1, 1);
    cfg.blockDim = dim3(FPS_THREADS, 1, 1);
    cfg.dynamicSmemBytes = 0;
    cfg.stream = 0;
    cudaLaunchAttribute attrs[1];
    attrs[0].id = cudaLaunchAttributeClusterDimension;
    attrs[0].val.clusterDim.x = CLUSTER;
    attrs[0].val.clusterDim.y = 1;
    attrs[0].val.clusterDim.z = 1;
    cfg.attrs = attrs;
    cfg.numAttrs = 1;
    cudaLaunchKernelEx(&cfg, fps_kernel);

    nbr_kernel<<<(CLOUDS * MCENT * 32) / 256, 256>>>(out, out_size);
    sample_kernel<<<(CLOUDS * MCENT + 255) / 256, 256>>>(pos, out, out_size);
}